// round 14
// baseline (speedup 1.0000x reference)
#include <cuda_runtime.h>
#include <cuda_fp16.h>

// CapsuleLayer dynamic routing, GB300 sm_103a
// inputs: [B, I, K] fp32 ; W: [J, I, D, K] fp32 ; out: [B, J, D] fp32
#define BB 256
#define II 2048
#define KK 8
#define JJ 10
#define DD 16
#define GI 16            // i's per uhat CTA (512 CTAs: balanced waves)
#define GB 64            // b's per uhat CTA (W traffic 42 MB total)
#define NGROUPS ((II + 2) / 3)   // 683 groups of 3 i's
#define RCTA_X 8
#define RWARPS 8

// Scratch (device globals; no allocation allowed)
__device__ __half g_uhat[(size_t)BB * II * JJ * DD]; // [b][i][j][d] fp16, 168MB
__device__ float g_s0[BB * JJ * DD];  // round-0 s (fused into producer, fp32)
__device__ float g_s1[BB * JJ * DD];
__device__ float g_s2[BB * JJ * DD];

// ---- f32x2 packed-FMA helpers (FFMA2 only reachable via PTX) -------------
static __device__ __forceinline__ unsigned long long pk2(float x, float y) {
    unsigned long long r;
    asm("mov.b64 %0, {%1, %2};" : "=l"(r) : "f"(x), "f"(y));
    return r;
}
static __device__ __forceinline__ void upk2(unsigned long long v, float& x, float& y) {
    asm("mov.b64 {%0, %1}, %2;" : "=f"(x), "=f"(y) : "l"(v));
}
static __device__ __forceinline__ unsigned long long fma2(
        unsigned long long a, unsigned long long b, unsigned long long c) {
    unsigned long long d;
    asm("fma.rn.f32x2 %0, %1, %2, %3;" : "=l"(d) : "l"(a), "l"(b), "l"(c));
    return d;
}

// ---------------------------------------------------------------------------
__global__ void init_kernel() {
    int t = blockIdx.x * blockDim.x + threadIdx.x;
    if (t < BB * JJ * DD) {
        g_s0[t] = 0.0f;
        g_s1[t] = 0.0f;
        g_s2[t] = 0.0f;
    }
}

// ---------------------------------------------------------------------------
// u_hat[b,i,j,d] = sum_k W[j,i,d,k] * in[b,i,k]  (fp32 FFMA2, stored fp16)
// PLUS fused round 0: s0[b,j,d] += 0.1 * sum_i u.
// CTA = 16 i x 64 b (512 CTAs: ~1.7 balanced waves vs R10's 256 CTAs that
// left 40 SMs half-loaded). Inputs staged ONCE (64 b x 128 floats). W double-
// buffered in smem, 1 bar/ii. Warp lanes share one b -> contiguous stores.
__global__ __launch_bounds__(320, 2)
void uhat_kernel(const float* __restrict__ inp, const float* __restrict__ W) {
    const int i0 = blockIdx.x * GI;
    const int b0 = blockIdx.y * GB;
    const int tid = threadIdx.x;

    __shared__ float in_s[GB][132];        // [b][ii*8+k]  33.8 KB
    __shared__ float w_s[2][40 * 36];      // [buf][slot*36+off] 11.5 KB

    const int grp = tid / 40;              // 0..7  (b-group)
    const int rem = tid % 40;              // (j,dq) slot
    const int j = rem >> 2;
    const int dq = rem & 3;

    // W stager mapping: thread t covers jj = t>>5, quarter r = t&31
    const int sjj = tid >> 5;              // 0..9
    const int sr  = tid & 31;
    const int sslot = sjj * 4 + (sr >> 3);
    const int soff  = (sr & 7) * 4;

    // stage W for i0 into buf 0 (coalesced 512B per warp)
    {
        float4 v = *(const float4*)(W + ((size_t)sjj * II + i0) * 128 + sr * 4);
        *(float4*)&w_s[0][sslot * 36 + soff] = v;
    }
    // stage inputs once: 64 b x 128 floats (16i x 8k), coalesced
    for (int t = tid; t < GB * 32; t += 320) {
        int b = t >> 5, q4 = t & 31;
        float4 v = *(const float4*)&inp[((size_t)(b0 + b) * II + i0) * KK + q4 * 4];
        *(float4*)&in_s[b][q4 * 4] = v;
    }
    __syncthreads();

    float sacc[32];
#pragma unroll
    for (int t = 0; t < 32; t++) sacc[t] = 0.f;

    int buf = 0;
    for (int ii = 0; ii < GI; ii++) {
        // issue next W load early (completes during compute below)
        float4 wnext;
        if (ii + 1 < GI)
            wnext = *(const float4*)(W + ((size_t)sjj * II + i0 + ii + 1) * 128 + sr * 4);

        // pack this ii's W from smem: 32 floats -> 16 d-pair packs
        unsigned long long p01[8], p23[8];
        {
            const float* wb = &w_s[buf][rem * 36];
            float4 w0 = *(const float4*)(wb + 0);
            float4 w1 = *(const float4*)(wb + 4);
            float4 w2 = *(const float4*)(wb + 8);
            float4 w3 = *(const float4*)(wb + 12);
            float4 w4 = *(const float4*)(wb + 16);
            float4 w5 = *(const float4*)(wb + 20);
            float4 w6 = *(const float4*)(wb + 24);
            float4 w7 = *(const float4*)(wb + 28);
            p01[0] = pk2(w0.x, w2.x); p01[1] = pk2(w0.y, w2.y);
            p01[2] = pk2(w0.z, w2.z); p01[3] = pk2(w0.w, w2.w);
            p01[4] = pk2(w1.x, w3.x); p01[5] = pk2(w1.y, w3.y);
            p01[6] = pk2(w1.z, w3.z); p01[7] = pk2(w1.w, w3.w);
            p23[0] = pk2(w4.x, w6.x); p23[1] = pk2(w4.y, w6.y);
            p23[2] = pk2(w4.z, w6.z); p23[3] = pk2(w4.w, w6.w);
            p23[4] = pk2(w5.x, w7.x); p23[5] = pk2(w5.y, w7.y);
            p23[6] = pk2(w5.z, w7.z); p23[7] = pk2(w5.w, w7.w);
        }

        const int iq = ii * 8;
        const int i = i0 + ii;
#pragma unroll
        for (int bo = 0; bo < 8; bo++) {
            const int b = bo * 8 + grp;
            float4 a0 = *(const float4*)&in_s[b][iq];       // warp broadcast
            float4 a1 = *(const float4*)&in_s[b][iq + 4];

            unsigned long long r01 = 0ull, r23 = 0ull;
            unsigned long long aa;
            aa = pk2(a0.x, a0.x); r01 = fma2(p01[0], aa, r01); r23 = fma2(p23[0], aa, r23);
            aa = pk2(a0.y, a0.y); r01 = fma2(p01[1], aa, r01); r23 = fma2(p23[1], aa, r23);
            aa = pk2(a0.z, a0.z); r01 = fma2(p01[2], aa, r01); r23 = fma2(p23[2], aa, r23);
            aa = pk2(a0.w, a0.w); r01 = fma2(p01[3], aa, r01); r23 = fma2(p23[3], aa, r23);
            aa = pk2(a1.x, a1.x); r01 = fma2(p01[4], aa, r01); r23 = fma2(p23[4], aa, r23);
            aa = pk2(a1.y, a1.y); r01 = fma2(p01[5], aa, r01); r23 = fma2(p23[5], aa, r23);
            aa = pk2(a1.z, a1.z); r01 = fma2(p01[6], aa, r01); r23 = fma2(p23[6], aa, r23);
            aa = pk2(a1.w, a1.w); r01 = fma2(p01[7], aa, r01); r23 = fma2(p23[7], aa, r23);

            float rx, ry, rz, rw;
            upk2(r01, rx, ry);
            upk2(r23, rz, rw);

            __half2 h0 = __float22half2_rn(make_float2(rx, ry));
            __half2 h1 = __float22half2_rn(make_float2(rz, rw));
            uint2 st;
            st.x = *reinterpret_cast<unsigned int*>(&h0);
            st.y = *reinterpret_cast<unsigned int*>(&h1);
            // warp lanes share b -> contiguous row segment -> ~2-3 wavefronts
            *(uint2*)&g_uhat[(((size_t)(b0 + b) * II + i) * JJ + j) * DD + dq * 4] = st;

            sacc[bo * 4 + 0] += rx;
            sacc[bo * 4 + 1] += ry;
            sacc[bo * 4 + 2] += rz;
            sacc[bo * 4 + 3] += rw;
        }

        if (ii + 1 < GI)
            *(float4*)&w_s[buf ^ 1][sslot * 36 + soff] = wnext;
        __syncthreads();
        buf ^= 1;
    }

    // fused round 0 contribution (spread REDGs, 5.2M total)
#pragma unroll
    for (int bo = 0; bo < 8; bo++) {
        const int b = b0 + bo * 8 + grp;
        float* sp = &g_s0[((size_t)b * JJ + j) * DD + dq * 4];
        atomicAdd(sp + 0, 0.1f * sacc[bo * 4 + 0]);
        atomicAdd(sp + 1, 0.1f * sacc[bo * 4 + 1]);
        atomicAdd(sp + 2, 0.1f * sacc[bo * 4 + 2]);
        atomicAdd(sp + 3, 0.1f * sacc[bo * 4 + 3]);
    }
}

// ---------------------------------------------------------------------------
static __device__ __forceinline__ void squash16_add(const float* __restrict__ s,
                                                    float* __restrict__ o) {
    float4 v0 = *(const float4*)(s + 0);
    float4 v1 = *(const float4*)(s + 4);
    float4 v2 = *(const float4*)(s + 8);
    float4 v3 = *(const float4*)(s + 12);
    float ss = v0.x * v0.x + v0.y * v0.y + v0.z * v0.z + v0.w * v0.w
             + v1.x * v1.x + v1.y * v1.y + v1.z * v1.z + v1.w * v1.w
             + v2.x * v2.x + v2.y * v2.y + v2.z * v2.z + v2.w * v2.w
             + v3.x * v3.x + v3.y * v3.y + v3.z * v3.z + v3.w * v3.w;
    float scale = ss / (1.0f + ss) * rsqrtf(ss + 1e-7f);
    o[0]  += scale * v0.x; o[1]  += scale * v0.y; o[2]  += scale * v0.z; o[3]  += scale * v0.w;
    o[4]  += scale * v1.x; o[5]  += scale * v1.y; o[6]  += scale * v1.z; o[7]  += scale * v1.w;
    o[8]  += scale * v2.x; o[9]  += scale * v2.y; o[10] += scale * v2.z; o[11] += scale * v2.w;
    o[12] += scale * v3.x; o[13] += scale * v3.y; o[14] += scale * v3.z; o[15] += scale * v3.w;
}

// ---------------------------------------------------------------------------
// One routing round, full batch (R13 measured-best: fp16 dot + fp16 acc).
__global__ __launch_bounds__(256, 2)
void route_kernel(int round) {
    const int b = blockIdx.y;
    const int tid = threadIdx.x;
    const int warp = tid >> 5;
    const int lane = tid & 31;
    const bool act = lane < 30;
    const int il = act ? lane / 10 : 2;
    const int j  = act ? lane % 10 : 0;
    const int il10 = il * 10;
    const int jm = (j >= 5) ? j - 5 : j;

    __shared__ float s_part[RWARPS][JJ][DD];   // 5 KB

    float os[16];
#pragma unroll
    for (int d = 0; d < 16; d++) os[d] = 0.f;
    squash16_add(&g_s0[(b * JJ + j) * DD], os);
    if (round == 2) squash16_add(&g_s1[(b * JJ + j) * DD], os);

    __half2 os_h2[8];
#pragma unroll
    for (int q = 0; q < 8; q++)
        os_h2[q] = __floats2half2_rn(os[q * 2], os[q * 2 + 1]);

    float* sOut = (round == 2) ? g_s2 : g_s1;

    __half2 acc_h2[8];
#pragma unroll
    for (int q = 0; q < 8; q++) acc_h2[q] = __float2half2_rn(0.f);

    const int wg = blockIdx.x * RWARPS + warp;
    const int NW = RCTA_X * RWARPS;

    const __half* ubase = g_uhat + (size_t)b * II * JJ * DD;

    auto ldgrp = [&](int gg, uint4& V0, uint4& V1) {
        V0 = make_uint4(0, 0, 0, 0);
        V1 = make_uint4(0, 0, 0, 0);
        int i = gg * 3 + il;
        if (act && gg < NGROUPS && i < II) {
            const uint4* up = (const uint4*)(ubase + ((size_t)i * JJ + j) * DD);
            V0 = up[0];
            V1 = up[1];
        }
    };

    uint4 A0, A1, B0, B1, C0, C1;
    ldgrp(wg, A0, A1);
    ldgrp(wg + NW, B0, B1);

    for (int g = wg; g < NGROUPS; g += NW) {
        ldgrp(g + 2 * NW, C0, C1);

        const __half2* ha = (const __half2*)&A0;
        const __half2* hb = (const __half2*)&A1;

        // logit dot in fp16: 8 HFMA2 over two chains
        __half2 d0 = __hmul2(ha[0], os_h2[0]);
        __half2 d1 = __hmul2(ha[1], os_h2[1]);
        d0 = __hfma2(ha[2], os_h2[2], d0);
        d1 = __hfma2(ha[3], os_h2[3], d1);
        d0 = __hfma2(hb[0], os_h2[4], d0);
        d1 = __hfma2(hb[1], os_h2[5], d1);
        d0 = __hfma2(hb[2], os_h2[6], d0);
        d1 = __hfma2(hb[3], os_h2[7], d1);
        __half2 ds = __hadd2(d0, d1);
        float lg = __low2float(ds) + __high2float(ds);
        float e = __expf(lg);

        // esum over 10 j's: 4-shfl log-depth tree
        float ep = e + __shfl_sync(0xffffffffu, e, il10 + ((j + 5) % 10));
        float q1 = ep + __shfl_sync(0xffffffffu, ep, il10 + ((jm + 1) % 5));
        float e4 = __shfl_sync(0xffffffffu, ep, il10 + ((jm + 4) % 5));
        float q2 = q1 + __shfl_sync(0xffffffffu, q1, il10 + ((jm + 2) % 5));
        float esum = q2 + e4;
        float c = __fdividef(e, esum);

        // acc += c * u in half2 (8 HFMA2)
        __half2 c2 = __float2half2_rn(c);
#pragma unroll
        for (int q = 0; q < 4; q++)
            acc_h2[q] = __hfma2(c2, ha[q], acc_h2[q]);
#pragma unroll
        for (int q = 0; q < 4; q++)
            acc_h2[4 + q] = __hfma2(c2, hb[q], acc_h2[4 + q]);

        A0 = B0; A1 = B1;
        B0 = C0; B1 = C1;
    }

    // convert to fp32 and reduce the 3 il-groups
    float acc[16];
#pragma unroll
    for (int q = 0; q < 8; q++) {
        float2 f = __half22float2(acc_h2[q]);
        acc[q * 2] = f.x;
        acc[q * 2 + 1] = f.y;
    }

#pragma unroll
    for (int d = 0; d < 16; d++) {
        float v  = acc[d];
        float v1 = __shfl_sync(0xffffffffu, v, lane + 10);
        float v2 = __shfl_sync(0xffffffffu, v, lane + 20);
        v = v + v1 + v2;
        if (lane < 10) s_part[warp][lane][d] = v;
    }
    __syncthreads();

    if (tid < JJ * DD) {
        int jj = tid >> 4, d = tid & 15;
        float t = 0.f;
#pragma unroll
        for (int w = 0; w < RWARPS; w++) t += s_part[w][jj][d];
        atomicAdd(&sOut[(b * JJ + jj) * DD + d], t);
    }
}

// ---------------------------------------------------------------------------
__global__ void squash_final_kernel(float* __restrict__ out) {
    int t = blockIdx.x * blockDim.x + threadIdx.x;   // (b*JJ + j)
    if (t >= BB * JJ) return;
    float o[16];
#pragma unroll
    for (int d = 0; d < 16; d++) o[d] = 0.f;
    squash16_add(&g_s2[t * DD], o);
#pragma unroll
    for (int q = 0; q < 4; q++) {
        float4 v = make_float4(o[q * 4], o[q * 4 + 1], o[q * 4 + 2], o[q * 4 + 3]);
        *(float4*)&out[t * DD + q * 4] = v;
    }
}

// ---------------------------------------------------------------------------
extern "C" void kernel_launch(void* const* d_in, const int* in_sizes, int n_in,
                              void* d_out, int out_size) {
    const float* inp = (const float*)d_in[0];
    const float* W   = (const float*)d_in[1];
    if (n_in >= 2 && in_sizes[0] == JJ * II * DD * KK) {
        const float* tmp = inp; inp = W; W = tmp;
    }
    float* out = (float*)d_out;

    init_kernel<<<(BB * JJ * DD + 255) / 256, 256>>>();
    uhat_kernel<<<dim3(II / GI, BB / GB), 320>>>(inp, W);
    route_kernel<<<dim3(RCTA_X, BB), 256>>>(1);
    route_kernel<<<dim3(RCTA_X, BB), 256>>>(2);
    squash_final_kernel<<<(BB * JJ + 255) / 256, 256>>>(out);
}

// round 15
// speedup vs baseline: 1.0375x; 1.0375x over previous
#include <cuda_runtime.h>
#include <cuda_fp16.h>

// CapsuleLayer dynamic routing, GB300 sm_103a
// inputs: [B, I, K] fp32 ; W: [J, I, D, K] fp32 ; out: [B, J, D] fp32
// R15 = measured-best composition: R10 producer (uhat ~83us) + R13 fp16 route
// (52.0us/pass). These never ran together before.
#define BB 256
#define II 2048
#define KK 8
#define JJ 10
#define DD 16
#define GI 32            // i's per uhat CTA (R10 measured-best)
#define GB 64            // b's per uhat CTA (W traffic 42 MB total)
#define NGROUPS ((II + 2) / 3)   // 683 groups of 3 i's
#define RCTA_X 8
#define RWARPS 8

// Scratch (device globals; no allocation allowed)
__device__ __half g_uhat[(size_t)BB * II * JJ * DD]; // [b][i][j][d] fp16, 168MB
__device__ float g_s0[BB * JJ * DD];  // round-0 s (fused into producer, fp32)
__device__ float g_s1[BB * JJ * DD];
__device__ float g_s2[BB * JJ * DD];

// ---- f32x2 packed-FMA helpers (FFMA2 only reachable via PTX) -------------
static __device__ __forceinline__ unsigned long long pk2(float x, float y) {
    unsigned long long r;
    asm("mov.b64 %0, {%1, %2};" : "=l"(r) : "f"(x), "f"(y));
    return r;
}
static __device__ __forceinline__ void upk2(unsigned long long v, float& x, float& y) {
    asm("mov.b64 {%0, %1}, %2;" : "=f"(x), "=f"(y) : "l"(v));
}
static __device__ __forceinline__ unsigned long long fma2(
        unsigned long long a, unsigned long long b, unsigned long long c) {
    unsigned long long d;
    asm("fma.rn.f32x2 %0, %1, %2, %3;" : "=l"(d) : "l"(a), "l"(b), "l"(c));
    return d;
}

// ---------------------------------------------------------------------------
__global__ void init_kernel() {
    int t = blockIdx.x * blockDim.x + threadIdx.x;
    if (t < BB * JJ * DD) {
        g_s0[t] = 0.0f;
        g_s1[t] = 0.0f;
        g_s2[t] = 0.0f;
    }
}

// ---------------------------------------------------------------------------
// u_hat[b,i,j,d] = sum_k W[j,i,d,k] * in[b,i,k]  (fp32 FFMA2, stored fp16)
// PLUS fused round 0: s0[b,j,d] += 0.1 * sum_i u.
// CTA = 32 i x 64 b (256 CTAs): W read 4x total = 42 MB. 320 thr = 8 b-groups
// x 40 (j,dq) slots; warp lanes share one b -> contiguous ~256B stores.
// W double-buffered in smem (1 bar/ii); inputs staged per 16-i half.
__global__ __launch_bounds__(320, 2)
void uhat_kernel(const float* __restrict__ inp, const float* __restrict__ W) {
    const int i0 = blockIdx.x * GI;
    const int b0 = blockIdx.y * GB;
    const int tid = threadIdx.x;

    __shared__ float in_s[GB][132];        // [b][(ii%16)*8+k]  33.8 KB
    __shared__ float w_s[2][40 * 36];      // [buf][slot*36+off] 11.5 KB

    const int grp = tid / 40;              // 0..7  (b-group)
    const int rem = tid % 40;              // (j,dq) slot
    const int j = rem >> 2;
    const int dq = rem & 3;

    // W stager mapping: thread t covers jj = t>>5, quarter r = t&31
    const int sjj = tid >> 5;              // 0..9
    const int sr  = tid & 31;
    const int sslot = sjj * 4 + (sr >> 3);
    const int soff  = (sr & 7) * 4;

    // stage W for i0 into buf 0 (coalesced 512B per warp)
    {
        float4 v = *(const float4*)(W + ((size_t)sjj * II + i0) * 128 + sr * 4);
        *(float4*)&w_s[0][sslot * 36 + soff] = v;
    }
    // stage inputs, first 16-i half: 64 b x 128 floats, coalesced
    for (int t = tid; t < GB * 32; t += 320) {
        int b = t >> 5, q4 = t & 31;
        float4 v = *(const float4*)&inp[((size_t)(b0 + b) * II + i0) * KK + q4 * 4];
        *(float4*)&in_s[b][q4 * 4] = v;
    }
    __syncthreads();

    float sacc[32];
#pragma unroll
    for (int t = 0; t < 32; t++) sacc[t] = 0.f;

    int buf = 0;
    for (int ii = 0; ii < GI; ii++) {
        if (ii == 16) {
            // previous bar guarantees first-half in_s fully consumed
            for (int t = tid; t < GB * 32; t += 320) {
                int b = t >> 5, q4 = t & 31;
                float4 v = *(const float4*)&inp[((size_t)(b0 + b) * II + i0 + 16) * KK + q4 * 4];
                *(float4*)&in_s[b][q4 * 4] = v;
            }
            __syncthreads();
        }

        // issue next W load early (completes during compute below)
        float4 wnext;
        if (ii + 1 < GI)
            wnext = *(const float4*)(W + ((size_t)sjj * II + i0 + ii + 1) * 128 + sr * 4);

        // pack this ii's W from smem: 32 floats -> 16 d-pair packs
        unsigned long long p01[8], p23[8];
        {
            const float* wb = &w_s[buf][rem * 36];
            float4 w0 = *(const float4*)(wb + 0);
            float4 w1 = *(const float4*)(wb + 4);
            float4 w2 = *(const float4*)(wb + 8);
            float4 w3 = *(const float4*)(wb + 12);
            float4 w4 = *(const float4*)(wb + 16);
            float4 w5 = *(const float4*)(wb + 20);
            float4 w6 = *(const float4*)(wb + 24);
            float4 w7 = *(const float4*)(wb + 28);
            p01[0] = pk2(w0.x, w2.x); p01[1] = pk2(w0.y, w2.y);
            p01[2] = pk2(w0.z, w2.z); p01[3] = pk2(w0.w, w2.w);
            p01[4] = pk2(w1.x, w3.x); p01[5] = pk2(w1.y, w3.y);
            p01[6] = pk2(w1.z, w3.z); p01[7] = pk2(w1.w, w3.w);
            p23[0] = pk2(w4.x, w6.x); p23[1] = pk2(w4.y, w6.y);
            p23[2] = pk2(w4.z, w6.z); p23[3] = pk2(w4.w, w6.w);
            p23[4] = pk2(w5.x, w7.x); p23[5] = pk2(w5.y, w7.y);
            p23[6] = pk2(w5.z, w7.z); p23[7] = pk2(w5.w, w7.w);
        }

        const int iq = (ii & 15) * 8;
        const int i = i0 + ii;
#pragma unroll
        for (int bo = 0; bo < 8; bo++) {
            const int b = bo * 8 + grp;
            float4 a0 = *(const float4*)&in_s[b][iq];       // warp broadcast
            float4 a1 = *(const float4*)&in_s[b][iq + 4];

            unsigned long long r01 = 0ull, r23 = 0ull;
            unsigned long long aa;
            aa = pk2(a0.x, a0.x); r01 = fma2(p01[0], aa, r01); r23 = fma2(p23[0], aa, r23);
            aa = pk2(a0.y, a0.y); r01 = fma2(p01[1], aa, r01); r23 = fma2(p23[1], aa, r23);
            aa = pk2(a0.z, a0.z); r01 = fma2(p01[2], aa, r01); r23 = fma2(p23[2], aa, r23);
            aa = pk2(a0.w, a0.w); r01 = fma2(p01[3], aa, r01); r23 = fma2(p23[3], aa, r23);
            aa = pk2(a1.x, a1.x); r01 = fma2(p01[4], aa, r01); r23 = fma2(p23[4], aa, r23);
            aa = pk2(a1.y, a1.y); r01 = fma2(p01[5], aa, r01); r23 = fma2(p23[5], aa, r23);
            aa = pk2(a1.z, a1.z); r01 = fma2(p01[6], aa, r01); r23 = fma2(p23[6], aa, r23);
            aa = pk2(a1.w, a1.w); r01 = fma2(p01[7], aa, r01); r23 = fma2(p23[7], aa, r23);

            float rx, ry, rz, rw;
            upk2(r01, rx, ry);
            upk2(r23, rz, rw);

            __half2 h0 = __float22half2_rn(make_float2(rx, ry));
            __half2 h1 = __float22half2_rn(make_float2(rz, rw));
            uint2 st;
            st.x = *reinterpret_cast<unsigned int*>(&h0);
            st.y = *reinterpret_cast<unsigned int*>(&h1);
            // warp lanes share b -> contiguous row segment -> ~2-3 wavefronts
            *(uint2*)&g_uhat[(((size_t)(b0 + b) * II + i) * JJ + j) * DD + dq * 4] = st;

            sacc[bo * 4 + 0] += rx;
            sacc[bo * 4 + 1] += ry;
            sacc[bo * 4 + 2] += rz;
            sacc[bo * 4 + 3] += rw;
        }

        if (ii + 1 < GI)
            *(float4*)&w_s[buf ^ 1][sslot * 36 + soff] = wnext;
        __syncthreads();
        buf ^= 1;
    }

    // fused round 0 contribution (spread REDGs, 2.6M total)
#pragma unroll
    for (int bo = 0; bo < 8; bo++) {
        const int b = b0 + bo * 8 + grp;
        float* sp = &g_s0[((size_t)b * JJ + j) * DD + dq * 4];
        atomicAdd(sp + 0, 0.1f * sacc[bo * 4 + 0]);
        atomicAdd(sp + 1, 0.1f * sacc[bo * 4 + 1]);
        atomicAdd(sp + 2, 0.1f * sacc[bo * 4 + 2]);
        atomicAdd(sp + 3, 0.1f * sacc[bo * 4 + 3]);
    }
}

// ---------------------------------------------------------------------------
static __device__ __forceinline__ void squash16_add(const float* __restrict__ s,
                                                    float* __restrict__ o) {
    float4 v0 = *(const float4*)(s + 0);
    float4 v1 = *(const float4*)(s + 4);
    float4 v2 = *(const float4*)(s + 8);
    float4 v3 = *(const float4*)(s + 12);
    float ss = v0.x * v0.x + v0.y * v0.y + v0.z * v0.z + v0.w * v0.w
             + v1.x * v1.x + v1.y * v1.y + v1.z * v1.z + v1.w * v1.w
             + v2.x * v2.x + v2.y * v2.y + v2.z * v2.z + v2.w * v2.w
             + v3.x * v3.x + v3.y * v3.y + v3.z * v3.z + v3.w * v3.w;
    float scale = ss / (1.0f + ss) * rsqrtf(ss + 1e-7f);
    o[0]  += scale * v0.x; o[1]  += scale * v0.y; o[2]  += scale * v0.z; o[3]  += scale * v0.w;
    o[4]  += scale * v1.x; o[5]  += scale * v1.y; o[6]  += scale * v1.z; o[7]  += scale * v1.w;
    o[8]  += scale * v2.x; o[9]  += scale * v2.y; o[10] += scale * v2.z; o[11] += scale * v2.w;
    o[12] += scale * v3.x; o[13] += scale * v3.y; o[14] += scale * v3.z; o[15] += scale * v3.w;
}

// ---------------------------------------------------------------------------
// One routing round, full batch (R13 measured-best: fp16 dot + fp16 acc,
// depth-3 prefetch, 4-shfl log-depth softmax; 52.0us/pass).
__global__ __launch_bounds__(256, 2)
void route_kernel(int round) {
    const int b = blockIdx.y;
    const int tid = threadIdx.x;
    const int warp = tid >> 5;
    const int lane = tid & 31;
    const bool act = lane < 30;
    const int il = act ? lane / 10 : 2;
    const int j  = act ? lane % 10 : 0;
    const int il10 = il * 10;
    const int jm = (j >= 5) ? j - 5 : j;

    __shared__ float s_part[RWARPS][JJ][DD];   // 5 KB

    float os[16];
#pragma unroll
    for (int d = 0; d < 16; d++) os[d] = 0.f;
    squash16_add(&g_s0[(b * JJ + j) * DD], os);
    if (round == 2) squash16_add(&g_s1[(b * JJ + j) * DD], os);

    __half2 os_h2[8];
#pragma unroll
    for (int q = 0; q < 8; q++)
        os_h2[q] = __floats2half2_rn(os[q * 2], os[q * 2 + 1]);

    float* sOut = (round == 2) ? g_s2 : g_s1;

    __half2 acc_h2[8];
#pragma unroll
    for (int q = 0; q < 8; q++) acc_h2[q] = __float2half2_rn(0.f);

    const int wg = blockIdx.x * RWARPS + warp;
    const int NW = RCTA_X * RWARPS;

    const __half* ubase = g_uhat + (size_t)b * II * JJ * DD;

    auto ldgrp = [&](int gg, uint4& V0, uint4& V1) {
        V0 = make_uint4(0, 0, 0, 0);
        V1 = make_uint4(0, 0, 0, 0);
        int i = gg * 3 + il;
        if (act && gg < NGROUPS && i < II) {
            const uint4* up = (const uint4*)(ubase + ((size_t)i * JJ + j) * DD);
            V0 = up[0];
            V1 = up[1];
        }
    };

    uint4 A0, A1, B0, B1, C0, C1;
    ldgrp(wg, A0, A1);
    ldgrp(wg + NW, B0, B1);

    for (int g = wg; g < NGROUPS; g += NW) {
        ldgrp(g + 2 * NW, C0, C1);

        const __half2* ha = (const __half2*)&A0;
        const __half2* hb = (const __half2*)&A1;

        // logit dot in fp16: 8 HFMA2 over two chains
        __half2 d0 = __hmul2(ha[0], os_h2[0]);
        __half2 d1 = __hmul2(ha[1], os_h2[1]);
        d0 = __hfma2(ha[2], os_h2[2], d0);
        d1 = __hfma2(ha[3], os_h2[3], d1);
        d0 = __hfma2(hb[0], os_h2[4], d0);
        d1 = __hfma2(hb[1], os_h2[5], d1);
        d0 = __hfma2(hb[2], os_h2[6], d0);
        d1 = __hfma2(hb[3], os_h2[7], d1);
        __half2 ds = __hadd2(d0, d1);
        float lg = __low2float(ds) + __high2float(ds);
        float e = __expf(lg);

        // esum over 10 j's: 4-shfl log-depth tree
        float ep = e + __shfl_sync(0xffffffffu, e, il10 + ((j + 5) % 10));
        float q1 = ep + __shfl_sync(0xffffffffu, ep, il10 + ((jm + 1) % 5));
        float e4 = __shfl_sync(0xffffffffu, ep, il10 + ((jm + 4) % 5));
        float q2 = q1 + __shfl_sync(0xffffffffu, q1, il10 + ((jm + 2) % 5));
        float esum = q2 + e4;
        float c = __fdividef(e, esum);

        // acc += c * u in half2 (8 HFMA2)
        __half2 c2 = __float2half2_rn(c);
#pragma unroll
        for (int q = 0; q < 4; q++)
            acc_h2[q] = __hfma2(c2, ha[q], acc_h2[q]);
#pragma unroll
        for (int q = 0; q < 4; q++)
            acc_h2[4 + q] = __hfma2(c2, hb[q], acc_h2[4 + q]);

        A0 = B0; A1 = B1;
        B0 = C0; B1 = C1;
    }

    // convert to fp32 and reduce the 3 il-groups
    float acc[16];
#pragma unroll
    for (int q = 0; q < 8; q++) {
        float2 f = __half22float2(acc_h2[q]);
        acc[q * 2] = f.x;
        acc[q * 2 + 1] = f.y;
    }

#pragma unroll
    for (int d = 0; d < 16; d++) {
        float v  = acc[d];
        float v1 = __shfl_sync(0xffffffffu, v, lane + 10);
        float v2 = __shfl_sync(0xffffffffu, v, lane + 20);
        v = v + v1 + v2;
        if (lane < 10) s_part[warp][lane][d] = v;
    }
    __syncthreads();

    if (tid < JJ * DD) {
        int jj = tid >> 4, d = tid & 15;
        float t = 0.f;
#pragma unroll
        for (int w = 0; w < RWARPS; w++) t += s_part[w][jj][d];
        atomicAdd(&sOut[(b * JJ + jj) * DD + d], t);
    }
}

// ---------------------------------------------------------------------------
__global__ void squash_final_kernel(float* __restrict__ out) {
    int t = blockIdx.x * blockDim.x + threadIdx.x;   // (b*JJ + j)
    if (t >= BB * JJ) return;
    float o[16];
#pragma unroll
    for (int d = 0; d < 16; d++) o[d] = 0.f;
    squash16_add(&g_s2[t * DD], o);
#pragma unroll
    for (int q = 0; q < 4; q++) {
        float4 v = make_float4(o[q * 4], o[q * 4 + 1], o[q * 4 + 2], o[q * 4 + 3]);
        *(float4*)&out[t * DD + q * 4] = v;
    }
}

// ---------------------------------------------------------------------------
extern "C" void kernel_launch(void* const* d_in, const int* in_sizes, int n_in,
                              void* d_out, int out_size) {
    const float* inp = (const float*)d_in[0];
    const float* W   = (const float*)d_in[1];
    if (n_in >= 2 && in_sizes[0] == JJ * II * DD * KK) {
        const float* tmp = inp; inp = W; W = tmp;
    }
    float* out = (float*)d_out;

    init_kernel<<<(BB * JJ * DD + 255) / 256, 256>>>();
    uhat_kernel<<<dim3(II / GI, BB / GB), 320>>>(inp, W);
    route_kernel<<<dim3(RCTA_X, BB), 256>>>(1);
    route_kernel<<<dim3(RCTA_X, BB), 256>>>(2);
    squash_final_kernel<<<(BB * JJ + 255) / 256, 256>>>(out);
}

// round 16
// speedup vs baseline: 1.0479x; 1.0100x over previous
#include <cuda_runtime.h>
#include <cuda_fp16.h>

// CapsuleLayer dynamic routing, GB300 sm_103a
// inputs: [B, I, K] fp32 ; W: [J, I, D, K] fp32 ; out: [B, J, D] fp32
// R16 = R15 producer (best measured) + dual-stream route (2 independent
// group chains per warp iteration -> 2x ILP on the dot/shfl/div chain).
#define BB 256
#define II 2048
#define KK 8
#define JJ 10
#define DD 16
#define GI 32            // i's per uhat CTA (R10/R15 measured-best)
#define GB 64            // b's per uhat CTA (W traffic 42 MB total)
#define NGROUPS ((II + 2) / 3)   // 683 groups of 3 i's
#define RCTA_X 8
#define RWARPS 8

// Scratch (device globals; no allocation allowed)
__device__ __half g_uhat[(size_t)BB * II * JJ * DD]; // [b][i][j][d] fp16, 168MB
__device__ float g_s0[BB * JJ * DD];  // round-0 s (fused into producer, fp32)
__device__ float g_s1[BB * JJ * DD];
__device__ float g_s2[BB * JJ * DD];

// ---- f32x2 packed-FMA helpers (FFMA2 only reachable via PTX) -------------
static __device__ __forceinline__ unsigned long long pk2(float x, float y) {
    unsigned long long r;
    asm("mov.b64 %0, {%1, %2};" : "=l"(r) : "f"(x), "f"(y));
    return r;
}
static __device__ __forceinline__ void upk2(unsigned long long v, float& x, float& y) {
    asm("mov.b64 {%0, %1}, %2;" : "=f"(x), "=f"(y) : "l"(v));
}
static __device__ __forceinline__ unsigned long long fma2(
        unsigned long long a, unsigned long long b, unsigned long long c) {
    unsigned long long d;
    asm("fma.rn.f32x2 %0, %1, %2, %3;" : "=l"(d) : "l"(a), "l"(b), "l"(c));
    return d;
}

// ---------------------------------------------------------------------------
__global__ void init_kernel() {
    int t = blockIdx.x * blockDim.x + threadIdx.x;
    if (t < BB * JJ * DD) {
        g_s0[t] = 0.0f;
        g_s1[t] = 0.0f;
        g_s2[t] = 0.0f;
    }
}

// ---------------------------------------------------------------------------
// u_hat[b,i,j,d] = sum_k W[j,i,d,k] * in[b,i,k]  (fp32 FFMA2, stored fp16)
// PLUS fused round 0: s0[b,j,d] += 0.1 * sum_i u.  (R15 verbatim)
__global__ __launch_bounds__(320, 2)
void uhat_kernel(const float* __restrict__ inp, const float* __restrict__ W) {
    const int i0 = blockIdx.x * GI;
    const int b0 = blockIdx.y * GB;
    const int tid = threadIdx.x;

    __shared__ float in_s[GB][132];        // [b][(ii%16)*8+k]  33.8 KB
    __shared__ float w_s[2][40 * 36];      // [buf][slot*36+off] 11.5 KB

    const int grp = tid / 40;              // 0..7  (b-group)
    const int rem = tid % 40;              // (j,dq) slot
    const int j = rem >> 2;
    const int dq = rem & 3;

    const int sjj = tid >> 5;              // 0..9
    const int sr  = tid & 31;
    const int sslot = sjj * 4 + (sr >> 3);
    const int soff  = (sr & 7) * 4;

    {
        float4 v = *(const float4*)(W + ((size_t)sjj * II + i0) * 128 + sr * 4);
        *(float4*)&w_s[0][sslot * 36 + soff] = v;
    }
    for (int t = tid; t < GB * 32; t += 320) {
        int b = t >> 5, q4 = t & 31;
        float4 v = *(const float4*)&inp[((size_t)(b0 + b) * II + i0) * KK + q4 * 4];
        *(float4*)&in_s[b][q4 * 4] = v;
    }
    __syncthreads();

    float sacc[32];
#pragma unroll
    for (int t = 0; t < 32; t++) sacc[t] = 0.f;

    int buf = 0;
    for (int ii = 0; ii < GI; ii++) {
        if (ii == 16) {
            for (int t = tid; t < GB * 32; t += 320) {
                int b = t >> 5, q4 = t & 31;
                float4 v = *(const float4*)&inp[((size_t)(b0 + b) * II + i0 + 16) * KK + q4 * 4];
                *(float4*)&in_s[b][q4 * 4] = v;
            }
            __syncthreads();
        }

        float4 wnext;
        if (ii + 1 < GI)
            wnext = *(const float4*)(W + ((size_t)sjj * II + i0 + ii + 1) * 128 + sr * 4);

        unsigned long long p01[8], p23[8];
        {
            const float* wb = &w_s[buf][rem * 36];
            float4 w0 = *(const float4*)(wb + 0);
            float4 w1 = *(const float4*)(wb + 4);
            float4 w2 = *(const float4*)(wb + 8);
            float4 w3 = *(const float4*)(wb + 12);
            float4 w4 = *(const float4*)(wb + 16);
            float4 w5 = *(const float4*)(wb + 20);
            float4 w6 = *(const float4*)(wb + 24);
            float4 w7 = *(const float4*)(wb + 28);
            p01[0] = pk2(w0.x, w2.x); p01[1] = pk2(w0.y, w2.y);
            p01[2] = pk2(w0.z, w2.z); p01[3] = pk2(w0.w, w2.w);
            p01[4] = pk2(w1.x, w3.x); p01[5] = pk2(w1.y, w3.y);
            p01[6] = pk2(w1.z, w3.z); p01[7] = pk2(w1.w, w3.w);
            p23[0] = pk2(w4.x, w6.x); p23[1] = pk2(w4.y, w6.y);
            p23[2] = pk2(w4.z, w6.z); p23[3] = pk2(w4.w, w6.w);
            p23[4] = pk2(w5.x, w7.x); p23[5] = pk2(w5.y, w7.y);
            p23[6] = pk2(w5.z, w7.z); p23[7] = pk2(w5.w, w7.w);
        }

        const int iq = (ii & 15) * 8;
        const int i = i0 + ii;
#pragma unroll
        for (int bo = 0; bo < 8; bo++) {
            const int b = bo * 8 + grp;
            float4 a0 = *(const float4*)&in_s[b][iq];
            float4 a1 = *(const float4*)&in_s[b][iq + 4];

            unsigned long long r01 = 0ull, r23 = 0ull;
            unsigned long long aa;
            aa = pk2(a0.x, a0.x); r01 = fma2(p01[0], aa, r01); r23 = fma2(p23[0], aa, r23);
            aa = pk2(a0.y, a0.y); r01 = fma2(p01[1], aa, r01); r23 = fma2(p23[1], aa, r23);
            aa = pk2(a0.z, a0.z); r01 = fma2(p01[2], aa, r01); r23 = fma2(p23[2], aa, r23);
            aa = pk2(a0.w, a0.w); r01 = fma2(p01[3], aa, r01); r23 = fma2(p23[3], aa, r23);
            aa = pk2(a1.x, a1.x); r01 = fma2(p01[4], aa, r01); r23 = fma2(p23[4], aa, r23);
            aa = pk2(a1.y, a1.y); r01 = fma2(p01[5], aa, r01); r23 = fma2(p23[5], aa, r23);
            aa = pk2(a1.z, a1.z); r01 = fma2(p01[6], aa, r01); r23 = fma2(p23[6], aa, r23);
            aa = pk2(a1.w, a1.w); r01 = fma2(p01[7], aa, r01); r23 = fma2(p23[7], aa, r23);

            float rx, ry, rz, rw;
            upk2(r01, rx, ry);
            upk2(r23, rz, rw);

            __half2 h0 = __float22half2_rn(make_float2(rx, ry));
            __half2 h1 = __float22half2_rn(make_float2(rz, rw));
            uint2 st;
            st.x = *reinterpret_cast<unsigned int*>(&h0);
            st.y = *reinterpret_cast<unsigned int*>(&h1);
            *(uint2*)&g_uhat[(((size_t)(b0 + b) * II + i) * JJ + j) * DD + dq * 4] = st;

            sacc[bo * 4 + 0] += rx;
            sacc[bo * 4 + 1] += ry;
            sacc[bo * 4 + 2] += rz;
            sacc[bo * 4 + 3] += rw;
        }

        if (ii + 1 < GI)
            *(float4*)&w_s[buf ^ 1][sslot * 36 + soff] = wnext;
        __syncthreads();
        buf ^= 1;
    }

#pragma unroll
    for (int bo = 0; bo < 8; bo++) {
        const int b = b0 + bo * 8 + grp;
        float* sp = &g_s0[((size_t)b * JJ + j) * DD + dq * 4];
        atomicAdd(sp + 0, 0.1f * sacc[bo * 4 + 0]);
        atomicAdd(sp + 1, 0.1f * sacc[bo * 4 + 1]);
        atomicAdd(sp + 2, 0.1f * sacc[bo * 4 + 2]);
        atomicAdd(sp + 3, 0.1f * sacc[bo * 4 + 3]);
    }
}

// ---------------------------------------------------------------------------
static __device__ __forceinline__ void squash16_add(const float* __restrict__ s,
                                                    float* __restrict__ o) {
    float4 v0 = *(const float4*)(s + 0);
    float4 v1 = *(const float4*)(s + 4);
    float4 v2 = *(const float4*)(s + 8);
    float4 v3 = *(const float4*)(s + 12);
    float ss = v0.x * v0.x + v0.y * v0.y + v0.z * v0.z + v0.w * v0.w
             + v1.x * v1.x + v1.y * v1.y + v1.z * v1.z + v1.w * v1.w
             + v2.x * v2.x + v2.y * v2.y + v2.z * v2.z + v2.w * v2.w
             + v3.x * v3.x + v3.y * v3.y + v3.z * v3.z + v3.w * v3.w;
    float scale = ss / (1.0f + ss) * rsqrtf(ss + 1e-7f);
    o[0]  += scale * v0.x; o[1]  += scale * v0.y; o[2]  += scale * v0.z; o[3]  += scale * v0.w;
    o[4]  += scale * v1.x; o[5]  += scale * v1.y; o[6]  += scale * v1.z; o[7]  += scale * v1.w;
    o[8]  += scale * v2.x; o[9]  += scale * v2.y; o[10] += scale * v2.z; o[11] += scale * v2.w;
    o[12] += scale * v3.x; o[13] += scale * v3.y; o[14] += scale * v3.z; o[15] += scale * v3.w;
}

// ---------------------------------------------------------------------------
// One routing round, full batch. DUAL-STREAM: each warp iteration processes
// two independent groups (g and g+NW) with fully duplicated registers and
// chains -> 2x ILP on the load->dot->exp->shfl-tree->div critical path.
// Out-of-range groups load guarded zeros (u=0 -> acc += c*0), so the phantom
// tail of stream 1 is harmless. Coverage wg + 64k is complete.
__global__ __launch_bounds__(256, 2)
void route_kernel(int round) {
    const int b = blockIdx.y;
    const int tid = threadIdx.x;
    const int warp = tid >> 5;
    const int lane = tid & 31;
    const bool act = lane < 30;
    const int il = act ? lane / 10 : 2;
    const int j  = act ? lane % 10 : 0;
    const int il10 = il * 10;
    const int jm = (j >= 5) ? j - 5 : j;

    __shared__ float s_part[RWARPS][JJ][DD];   // 5 KB

    float os[16];
#pragma unroll
    for (int d = 0; d < 16; d++) os[d] = 0.f;
    squash16_add(&g_s0[(b * JJ + j) * DD], os);
    if (round == 2) squash16_add(&g_s1[(b * JJ + j) * DD], os);

    __half2 os_h2[8];
#pragma unroll
    for (int q = 0; q < 8; q++)
        os_h2[q] = __floats2half2_rn(os[q * 2], os[q * 2 + 1]);

    float* sOut = (round == 2) ? g_s2 : g_s1;

    __half2 acc_h2[8];
#pragma unroll
    for (int q = 0; q < 8; q++) acc_h2[q] = __float2half2_rn(0.f);

    const int wg = blockIdx.x * RWARPS + warp;
    const int NW = RCTA_X * RWARPS;

    const __half* ubase = g_uhat + (size_t)b * II * JJ * DD;

    auto ldgrp = [&](int gg, uint4& V0, uint4& V1) {
        V0 = make_uint4(0, 0, 0, 0);
        V1 = make_uint4(0, 0, 0, 0);
        int i = gg * 3 + il;
        if (act && gg < NGROUPS && i < II) {
            const uint4* up = (const uint4*)(ubase + ((size_t)i * JJ + j) * DD);
            V0 = up[0];
            V1 = up[1];
        }
    };

    // stream0: A (current), P (next). stream1: E (current), Q (next).
    uint4 A0, A1, E0, E1, P0, P1, Q0, Q1;
    ldgrp(wg,          A0, A1);
    ldgrp(wg + NW,     E0, E1);
    ldgrp(wg + 2 * NW, P0, P1);
    ldgrp(wg + 3 * NW, Q0, Q1);

    for (int g = wg; g < NGROUPS; g += 2 * NW) {
        const __half2* ha = (const __half2*)&A0;
        const __half2* hb = (const __half2*)&A1;
        const __half2* he = (const __half2*)&E0;
        const __half2* hf = (const __half2*)&E1;

        // interleaved fp16 logit dots (two independent chains each)
        __half2 x0 = __hmul2(ha[0], os_h2[0]);
        __half2 y0 = __hmul2(he[0], os_h2[0]);
        __half2 x1 = __hmul2(ha[1], os_h2[1]);
        __half2 y1 = __hmul2(he[1], os_h2[1]);
        x0 = __hfma2(ha[2], os_h2[2], x0);  y0 = __hfma2(he[2], os_h2[2], y0);
        x1 = __hfma2(ha[3], os_h2[3], x1);  y1 = __hfma2(he[3], os_h2[3], y1);
        x0 = __hfma2(hb[0], os_h2[4], x0);  y0 = __hfma2(hf[0], os_h2[4], y0);
        x1 = __hfma2(hb[1], os_h2[5], x1);  y1 = __hfma2(hf[1], os_h2[5], y1);
        x0 = __hfma2(hb[2], os_h2[6], x0);  y0 = __hfma2(hf[2], os_h2[6], y0);
        x1 = __hfma2(hb[3], os_h2[7], x1);  y1 = __hfma2(hf[3], os_h2[7], y1);
        __half2 xs = __hadd2(x0, x1);
        __half2 ys = __hadd2(y0, y1);
        float lgx = __low2float(xs) + __high2float(xs);
        float lgy = __low2float(ys) + __high2float(ys);
        float ex = __expf(lgx);
        float ey = __expf(lgy);

        // two interleaved 4-shfl softmax trees
        float epx = ex + __shfl_sync(0xffffffffu, ex, il10 + ((j + 5) % 10));
        float epy = ey + __shfl_sync(0xffffffffu, ey, il10 + ((j + 5) % 10));
        float q1x = epx + __shfl_sync(0xffffffffu, epx, il10 + ((jm + 1) % 5));
        float q1y = epy + __shfl_sync(0xffffffffu, epy, il10 + ((jm + 1) % 5));
        float e4x = __shfl_sync(0xffffffffu, epx, il10 + ((jm + 4) % 5));
        float e4y = __shfl_sync(0xffffffffu, epy, il10 + ((jm + 4) % 5));
        float q2x = q1x + __shfl_sync(0xffffffffu, q1x, il10 + ((jm + 2) % 5));
        float q2y = q1y + __shfl_sync(0xffffffffu, q1y, il10 + ((jm + 2) % 5));
        float cx = __fdividef(ex, q2x + e4x);
        float cy = __fdividef(ey, q2y + e4y);

        __half2 cx2 = __float2half2_rn(cx);
        __half2 cy2 = __float2half2_rn(cy);
#pragma unroll
        for (int q = 0; q < 4; q++) {
            acc_h2[q]     = __hfma2(cx2, ha[q], acc_h2[q]);
            acc_h2[4 + q] = __hfma2(cx2, hb[q], acc_h2[4 + q]);
        }
#pragma unroll
        for (int q = 0; q < 4; q++) {
            acc_h2[q]     = __hfma2(cy2, he[q], acc_h2[q]);
            acc_h2[4 + q] = __hfma2(cy2, hf[q], acc_h2[4 + q]);
        }

        // rotate and prefetch two iterations ahead
        A0 = P0; A1 = P1;
        E0 = Q0; E1 = Q1;
        ldgrp(g + 4 * NW, P0, P1);
        ldgrp(g + 5 * NW, Q0, Q1);
    }

    // convert to fp32 and reduce the 3 il-groups
    float acc[16];
#pragma unroll
    for (int q = 0; q < 8; q++) {
        float2 f = __half22float2(acc_h2[q]);
        acc[q * 2] = f.x;
        acc[q * 2 + 1] = f.y;
    }

#pragma unroll
    for (int d = 0; d < 16; d++) {
        float v  = acc[d];
        float v1 = __shfl_sync(0xffffffffu, v, lane + 10);
        float v2 = __shfl_sync(0xffffffffu, v, lane + 20);
        v = v + v1 + v2;
        if (lane < 10) s_part[warp][lane][d] = v;
    }
    __syncthreads();

    if (tid < JJ * DD) {
        int jj = tid >> 4, d = tid & 15;
        float t = 0.f;
#pragma unroll
        for (int w = 0; w < RWARPS; w++) t += s_part[w][jj][d];
        atomicAdd(&sOut[(b * JJ + jj) * DD + d], t);
    }
}

// ---------------------------------------------------------------------------
__global__ void squash_final_kernel(float* __restrict__ out) {
    int t = blockIdx.x * blockDim.x + threadIdx.x;   // (b*JJ + j)
    if (t >= BB * JJ) return;
    float o[16];
#pragma unroll
    for (int d = 0; d < 16; d++) o[d] = 0.f;
    squash16_add(&g_s2[t * DD], o);
#pragma unroll
    for (int q = 0; q < 4; q++) {
        float4 v = make_float4(o[q * 4], o[q * 4 + 1], o[q * 4 + 2], o[q * 4 + 3]);
        *(float4*)&out[t * DD + q * 4] = v;
    }
}

// ---------------------------------------------------------------------------
extern "C" void kernel_launch(void* const* d_in, const int* in_sizes, int n_in,
                              void* d_out, int out_size) {
    const float* inp = (const float*)d_in[0];
    const float* W   = (const float*)d_in[1];
    if (n_in >= 2 && in_sizes[0] == JJ * II * DD * KK) {
        const float* tmp = inp; inp = W; W = tmp;
    }
    float* out = (float*)d_out;

    init_kernel<<<(BB * JJ * DD + 255) / 256, 256>>>();
    uhat_kernel<<<dim3(II / GI, BB / GB), 320>>>(inp, W);
    route_kernel<<<dim3(RCTA_X, BB), 256>>>(1);
    route_kernel<<<dim3(RCTA_X, BB), 256>>>(2);
    squash_final_kernel<<<(BB * JJ + 255) / 256, 256>>>(out);
}

// round 17
// speedup vs baseline: 1.0553x; 1.0071x over previous
#include <cuda_runtime.h>
#include <cuda_fp16.h>

// CapsuleLayer dynamic routing, GB300 sm_103a
// inputs: [B, I, K] fp32 ; W: [J, I, D, K] fp32 ; out: [B, J, D] fp32
// R17 = producer with PER-WARP W pipeline (no per-ii CTA barrier: warp w owns
// j=w, W row per i is one contiguous 512B block -> private double buffer,
// syncwarp only) + dual-stream route with PACKED fp16 esum tree (4 shfls).
#define BB 256
#define II 2048
#define KK 8
#define JJ 10
#define DD 16
#define GI 32            // i's per uhat CTA
#define GB 64            // b's per uhat CTA (W traffic 42 MB total)
#define NGROUPS ((II + 2) / 3)   // 683 groups of 3 i's
#define RCTA_X 8
#define RWARPS 8

// Scratch (device globals; no allocation allowed)
__device__ __half g_uhat[(size_t)BB * II * JJ * DD]; // [b][i][j][d] fp16, 168MB
__device__ float g_s0[BB * JJ * DD];  // round-0 s (fused into producer, fp32)
__device__ float g_s1[BB * JJ * DD];
__device__ float g_s2[BB * JJ * DD];

// ---- f32x2 packed-FMA helpers (FFMA2 only reachable via PTX) -------------
static __device__ __forceinline__ unsigned long long pk2(float x, float y) {
    unsigned long long r;
    asm("mov.b64 %0, {%1, %2};" : "=l"(r) : "f"(x), "f"(y));
    return r;
}
static __device__ __forceinline__ void upk2(unsigned long long v, float& x, float& y) {
    asm("mov.b64 {%0, %1}, %2;" : "=f"(x), "=f"(y) : "l"(v));
}
static __device__ __forceinline__ unsigned long long fma2(
        unsigned long long a, unsigned long long b, unsigned long long c) {
    unsigned long long d;
    asm("fma.rn.f32x2 %0, %1, %2, %3;" : "=l"(d) : "l"(a), "l"(b), "l"(c));
    return d;
}
static __device__ __forceinline__ __half2 h2shfl(__half2 v, int src) {
    unsigned u = *reinterpret_cast<unsigned*>(&v);
    u = __shfl_sync(0xffffffffu, u, src);
    return *reinterpret_cast<__half2*>(&u);
}

// ---------------------------------------------------------------------------
__global__ void init_kernel() {
    int t = blockIdx.x * blockDim.x + threadIdx.x;
    if (t < BB * JJ * DD) {
        g_s0[t] = 0.0f;
        g_s1[t] = 0.0f;
        g_s2[t] = 0.0f;
    }
}

// ---------------------------------------------------------------------------
// u_hat[b,i,j,d] = sum_k W[j,i,d,k] * in[b,i,k]  (fp32 FFMA2, stored fp16)
// PLUS fused round 0: s0[b,j,d] += 0.1 * sum_i u.
// CTA = 32 i x 64 b. 320 thr = 10 warps; WARP w OWNS j = w. Lane: grp=lane&7
// (b-group), dq=(lane>>3)&3. W[j,i] = 512B contiguous -> each warp runs a
// private double-buffered W pipeline (1 LDG.128 + 1 STS.128 + syncwarp per i)
// with NO CTA barriers except the two input-half restage points.
__global__ __launch_bounds__(320, 2)
void uhat_kernel(const float* __restrict__ inp, const float* __restrict__ W) {
    const int i0 = blockIdx.x * GI;
    const int b0 = blockIdx.y * GB;
    const int tid = threadIdx.x;

    __shared__ float in_s[GB][132];          // [b][(ii%16)*8+k]  33.8 KB
    __shared__ float w_slab[JJ][2][128];     // per-warp W double buffer, 10 KB

    const int warp = tid >> 5;               // == j
    const int lane = tid & 31;
    const int grp = lane & 7;                 // b-group
    const int dq = (lane >> 3) & 3;           // d-quad
    const int j = warp;

    const float* wrow = W + ((size_t)j * II + i0) * 128;

    // stage W for i0 into buf 0: ONE LDG.128 per warp (512B coalesced)
    {
        float4 v = *(const float4*)(wrow + lane * 4);
        *(float4*)&w_slab[j][0][lane * 4] = v;
    }
    // stage inputs, first 16-i half: 64 b x 128 floats, coalesced
    for (int t = tid; t < GB * 32; t += 320) {
        int b = t >> 5, q4 = t & 31;
        float4 v = *(const float4*)&inp[((size_t)(b0 + b) * II + i0) * KK + q4 * 4];
        *(float4*)&in_s[b][q4 * 4] = v;
    }
    __syncthreads();

    float sacc[32];
#pragma unroll
    for (int t = 0; t < 32; t++) sacc[t] = 0.f;

    int buf = 0;
    for (int ii = 0; ii < GI; ii++) {
        if (ii == 16) {
            __syncthreads();   // all warps done reading first input half
            for (int t = tid; t < GB * 32; t += 320) {
                int b = t >> 5, q4 = t & 31;
                float4 v = *(const float4*)&inp[((size_t)(b0 + b) * II + i0 + 16) * KK + q4 * 4];
                *(float4*)&in_s[b][q4 * 4] = v;
            }
            __syncthreads();
        }

        // issue next W row load early (one LDG.128, overlaps compute)
        float4 wnext;
        if (ii + 1 < GI)
            wnext = *(const float4*)(wrow + (size_t)(ii + 1) * 128 + lane * 4);

        // pack this ii's W (this lane's dq region): 32 floats -> 16 packs
        unsigned long long p01[8], p23[8];
        {
            const float* wb = &w_slab[j][buf][dq * 32];
            float4 w0 = *(const float4*)(wb + 0);
            float4 w1 = *(const float4*)(wb + 4);
            float4 w2 = *(const float4*)(wb + 8);
            float4 w3 = *(const float4*)(wb + 12);
            float4 w4 = *(const float4*)(wb + 16);
            float4 w5 = *(const float4*)(wb + 20);
            float4 w6 = *(const float4*)(wb + 24);
            float4 w7 = *(const float4*)(wb + 28);
            p01[0] = pk2(w0.x, w2.x); p01[1] = pk2(w0.y, w2.y);
            p01[2] = pk2(w0.z, w2.z); p01[3] = pk2(w0.w, w2.w);
            p01[4] = pk2(w1.x, w3.x); p01[5] = pk2(w1.y, w3.y);
            p01[6] = pk2(w1.z, w3.z); p01[7] = pk2(w1.w, w3.w);
            p23[0] = pk2(w4.x, w6.x); p23[1] = pk2(w4.y, w6.y);
            p23[2] = pk2(w4.z, w6.z); p23[3] = pk2(w4.w, w6.w);
            p23[4] = pk2(w5.x, w7.x); p23[5] = pk2(w5.y, w7.y);
            p23[6] = pk2(w5.z, w7.z); p23[7] = pk2(w5.w, w7.w);
        }

        const int iq = (ii & 15) * 8;
        const int i = i0 + ii;
#pragma unroll
        for (int bo = 0; bo < 8; bo++) {
            const int b = bo * 8 + grp;
            float4 a0 = *(const float4*)&in_s[b][iq];       // warp broadcast
            float4 a1 = *(const float4*)&in_s[b][iq + 4];

            unsigned long long r01 = 0ull, r23 = 0ull;
            unsigned long long aa;
            aa = pk2(a0.x, a0.x); r01 = fma2(p01[0], aa, r01); r23 = fma2(p23[0], aa, r23);
            aa = pk2(a0.y, a0.y); r01 = fma2(p01[1], aa, r01); r23 = fma2(p23[1], aa, r23);
            aa = pk2(a0.z, a0.z); r01 = fma2(p01[2], aa, r01); r23 = fma2(p23[2], aa, r23);
            aa = pk2(a0.w, a0.w); r01 = fma2(p01[3], aa, r01); r23 = fma2(p23[3], aa, r23);
            aa = pk2(a1.x, a1.x); r01 = fma2(p01[4], aa, r01); r23 = fma2(p23[4], aa, r23);
            aa = pk2(a1.y, a1.y); r01 = fma2(p01[5], aa, r01); r23 = fma2(p23[5], aa, r23);
            aa = pk2(a1.z, a1.z); r01 = fma2(p01[6], aa, r01); r23 = fma2(p23[6], aa, r23);
            aa = pk2(a1.w, a1.w); r01 = fma2(p01[7], aa, r01); r23 = fma2(p23[7], aa, r23);

            float rx, ry, rz, rw;
            upk2(r01, rx, ry);
            upk2(r23, rz, rw);

            __half2 h0 = __float22half2_rn(make_float2(rx, ry));
            __half2 h1 = __float22half2_rn(make_float2(rz, rw));
            uint2 st;
            st.x = *reinterpret_cast<unsigned int*>(&h0);
            st.y = *reinterpret_cast<unsigned int*>(&h1);
            // warp lanes share b -> contiguous row segment -> ~2-3 wavefronts
            *(uint2*)&g_uhat[(((size_t)(b0 + b) * II + i) * JJ + j) * DD + dq * 4] = st;

            sacc[bo * 4 + 0] += rx;
            sacc[bo * 4 + 1] += ry;
            sacc[bo * 4 + 2] += rz;
            sacc[bo * 4 + 3] += rw;
        }

        if (ii + 1 < GI)
            *(float4*)&w_slab[j][buf ^ 1][lane * 4] = wnext;
        __syncwarp();      // warp-private pipeline: no CTA barrier
        buf ^= 1;
    }

    // fused round 0 contribution (spread REDGs, 2.6M total)
#pragma unroll
    for (int bo = 0; bo < 8; bo++) {
        const int b = b0 + bo * 8 + grp;
        float* sp = &g_s0[((size_t)b * JJ + j) * DD + dq * 4];
        atomicAdd(sp + 0, 0.1f * sacc[bo * 4 + 0]);
        atomicAdd(sp + 1, 0.1f * sacc[bo * 4 + 1]);
        atomicAdd(sp + 2, 0.1f * sacc[bo * 4 + 2]);
        atomicAdd(sp + 3, 0.1f * sacc[bo * 4 + 3]);
    }
}

// ---------------------------------------------------------------------------
static __device__ __forceinline__ void squash16_add(const float* __restrict__ s,
                                                    float* __restrict__ o) {
    float4 v0 = *(const float4*)(s + 0);
    float4 v1 = *(const float4*)(s + 4);
    float4 v2 = *(const float4*)(s + 8);
    float4 v3 = *(const float4*)(s + 12);
    float ss = v0.x * v0.x + v0.y * v0.y + v0.z * v0.z + v0.w * v0.w
             + v1.x * v1.x + v1.y * v1.y + v1.z * v1.z + v1.w * v1.w
             + v2.x * v2.x + v2.y * v2.y + v2.z * v2.z + v2.w * v2.w
             + v3.x * v3.x + v3.y * v3.y + v3.z * v3.z + v3.w * v3.w;
    float scale = ss / (1.0f + ss) * rsqrtf(ss + 1e-7f);
    o[0]  += scale * v0.x; o[1]  += scale * v0.y; o[2]  += scale * v0.z; o[3]  += scale * v0.w;
    o[4]  += scale * v1.x; o[5]  += scale * v1.y; o[6]  += scale * v1.z; o[7]  += scale * v1.w;
    o[8]  += scale * v2.x; o[9]  += scale * v2.y; o[10] += scale * v2.z; o[11] += scale * v2.w;
    o[12] += scale * v3.x; o[13] += scale * v3.y; o[14] += scale * v3.z; o[15] += scale * v3.w;
}

// ---------------------------------------------------------------------------
// One routing round, full batch. Dual-stream (2 groups/iter) with PACKED
// fp16 esum tree: both streams' exps travel in one half2 -> 4 shfls/iter.
__global__ __launch_bounds__(256, 2)
void route_kernel(int round) {
    const int b = blockIdx.y;
    const int tid = threadIdx.x;
    const int warp = tid >> 5;
    const int lane = tid & 31;
    const bool act = lane < 30;
    const int il = act ? lane / 10 : 2;
    const int j  = act ? lane % 10 : 0;
    const int il10 = il * 10;
    const int jm = (j >= 5) ? j - 5 : j;

    __shared__ float s_part[RWARPS][JJ][DD];   // 5 KB

    float os[16];
#pragma unroll
    for (int d = 0; d < 16; d++) os[d] = 0.f;
    squash16_add(&g_s0[(b * JJ + j) * DD], os);
    if (round == 2) squash16_add(&g_s1[(b * JJ + j) * DD], os);

    __half2 os_h2[8];
#pragma unroll
    for (int q = 0; q < 8; q++)
        os_h2[q] = __floats2half2_rn(os[q * 2], os[q * 2 + 1]);

    float* sOut = (round == 2) ? g_s2 : g_s1;

    __half2 acc_h2[8];
#pragma unroll
    for (int q = 0; q < 8; q++) acc_h2[q] = __float2half2_rn(0.f);

    const int wg = blockIdx.x * RWARPS + warp;
    const int NW = RCTA_X * RWARPS;

    const __half* ubase = g_uhat + (size_t)b * II * JJ * DD;

    auto ldgrp = [&](int gg, uint4& V0, uint4& V1) {
        V0 = make_uint4(0, 0, 0, 0);
        V1 = make_uint4(0, 0, 0, 0);
        int i = gg * 3 + il;
        if (act && gg < NGROUPS && i < II) {
            const uint4* up = (const uint4*)(ubase + ((size_t)i * JJ + j) * DD);
            V0 = up[0];
            V1 = up[1];
        }
    };

    // stream0: A (current), P (next). stream1: E (current), Q (next).
    uint4 A0, A1, E0, E1, P0, P1, Q0, Q1;
    ldgrp(wg,          A0, A1);
    ldgrp(wg + NW,     E0, E1);
    ldgrp(wg + 2 * NW, P0, P1);
    ldgrp(wg + 3 * NW, Q0, Q1);

    for (int g = wg; g < NGROUPS; g += 2 * NW) {
        const __half2* ha = (const __half2*)&A0;
        const __half2* hb = (const __half2*)&A1;
        const __half2* he = (const __half2*)&E0;
        const __half2* hf = (const __half2*)&E1;

        // interleaved fp16 logit dots (two independent chains each)
        __half2 x0 = __hmul2(ha[0], os_h2[0]);
        __half2 y0 = __hmul2(he[0], os_h2[0]);
        __half2 x1 = __hmul2(ha[1], os_h2[1]);
        __half2 y1 = __hmul2(he[1], os_h2[1]);
        x0 = __hfma2(ha[2], os_h2[2], x0);  y0 = __hfma2(he[2], os_h2[2], y0);
        x1 = __hfma2(ha[3], os_h2[3], x1);  y1 = __hfma2(he[3], os_h2[3], y1);
        x0 = __hfma2(hb[0], os_h2[4], x0);  y0 = __hfma2(hf[0], os_h2[4], y0);
        x1 = __hfma2(hb[1], os_h2[5], x1);  y1 = __hfma2(hf[1], os_h2[5], y1);
        x0 = __hfma2(hb[2], os_h2[6], x0);  y0 = __hfma2(hf[2], os_h2[6], y0);
        x1 = __hfma2(hb[3], os_h2[7], x1);  y1 = __hfma2(hf[3], os_h2[7], y1);
        __half2 xs = __hadd2(x0, x1);
        __half2 ys = __hadd2(y0, y1);
        float lgx = __low2float(xs) + __high2float(xs);
        float lgy = __low2float(ys) + __high2float(ys);
        float ex = __expf(lgx);
        float ey = __expf(lgy);

        // packed esum: both streams share one 4-shfl fp16 tree
        __half2 e2 = __floats2half2_rn(ex, ey);
        __half2 ep = __hadd2(e2, h2shfl(e2, il10 + ((j + 5) % 10)));
        __half2 q1 = __hadd2(ep, h2shfl(ep, il10 + ((jm + 1) % 5)));
        __half2 e4 = h2shfl(ep, il10 + ((jm + 4) % 5));
        __half2 q2 = __hadd2(q1, h2shfl(q1, il10 + ((jm + 2) % 5)));
        __half2 es2 = __hadd2(q2, e4);
        float cx = __fdividef(ex, __low2float(es2));
        float cy = __fdividef(ey, __high2float(es2));

        __half2 cx2 = __float2half2_rn(cx);
        __half2 cy2 = __float2half2_rn(cy);
#pragma unroll
        for (int q = 0; q < 4; q++) {
            acc_h2[q]     = __hfma2(cx2, ha[q], acc_h2[q]);
            acc_h2[4 + q] = __hfma2(cx2, hb[q], acc_h2[4 + q]);
        }
#pragma unroll
        for (int q = 0; q < 4; q++) {
            acc_h2[q]     = __hfma2(cy2, he[q], acc_h2[q]);
            acc_h2[4 + q] = __hfma2(cy2, hf[q], acc_h2[4 + q]);
        }

        // rotate and prefetch two iterations ahead
        A0 = P0; A1 = P1;
        E0 = Q0; E1 = Q1;
        ldgrp(g + 4 * NW, P0, P1);
        ldgrp(g + 5 * NW, Q0, Q1);
    }

    // convert to fp32 and reduce the 3 il-groups
    float acc[16];
#pragma unroll
    for (int q = 0; q < 8; q++) {
        float2 f = __half22float2(acc_h2[q]);
        acc[q * 2] = f.x;
        acc[q * 2 + 1] = f.y;
    }

#pragma unroll
    for (int d = 0; d < 16; d++) {
        float v  = acc[d];
        float v1 = __shfl_sync(0xffffffffu, v, lane + 10);
        float v2 = __shfl_sync(0xffffffffu, v, lane + 20);
        v = v + v1 + v2;
        if (lane < 10) s_part[warp][lane][d] = v;
    }
    __syncthreads();

    if (tid < JJ * DD) {
        int jj = tid >> 4, d = tid & 15;
        float t = 0.f;
#pragma unroll
        for (int w = 0; w < RWARPS; w++) t += s_part[w][jj][d];
        atomicAdd(&sOut[(b * JJ + jj) * DD + d], t);
    }
}

// ---------------------------------------------------------------------------
__global__ void squash_final_kernel(float* __restrict__ out) {
    int t = blockIdx.x * blockDim.x + threadIdx.x;   // (b*JJ + j)
    if (t >= BB * JJ) return;
    float o[16];
#pragma unroll
    for (int d = 0; d < 16; d++) o[d] = 0.f;
    squash16_add(&g_s2[t * DD], o);
#pragma unroll
    for (int q = 0; q < 4; q++) {
        float4 v = make_float4(o[q * 4], o[q * 4 + 1], o[q * 4 + 2], o[q * 4 + 3]);
        *(float4*)&out[t * DD + q * 4] = v;
    }
}

// ---------------------------------------------------------------------------
extern "C" void kernel_launch(void* const* d_in, const int* in_sizes, int n_in,
                              void* d_out, int out_size) {
    const float* inp = (const float*)d_in[0];
    const float* W   = (const float*)d_in[1];
    if (n_in >= 2 && in_sizes[0] == JJ * II * DD * KK) {
        const float* tmp = inp; inp = W; W = tmp;
    }
    float* out = (float*)d_out;

    init_kernel<<<(BB * JJ * DD + 255) / 256, 256>>>();
    uhat_kernel<<<dim3(II / GI, BB / GB), 320>>>(inp, W);
    route_kernel<<<dim3(RCTA_X, BB), 256>>>(1);
    route_kernel<<<dim3(RCTA_X, BB), 256>>>(2);
    squash_final_kernel<<<(BB * JJ + 255) / 256, 256>>>(out);
}